// round 15
// baseline (speedup 1.0000x reference)
#include <cuda_runtime.h>
#include <cuda_fp16.h>
#include <cstdint>

#define BATCH 16
#define CIN   128
#define COUT  256
#define HW    56

__device__ __align__(16) __half g_xh[BATCH * HW * HW * CIN]; // NHWC fp16 ints (12.8MB)
__device__ __align__(16) __half g_wh[9 * COUT * CIN];        // [tap][o][c] fp16 = w/256

__device__ __forceinline__ uint32_t smem_u32(const void* p) {
    uint32_t a;
    asm("{ .reg .u64 t; cvta.to.shared.u64 t, %1; cvt.u32.u64 %0, t; }" : "=r"(a) : "l"(p));
    return a;
}

// ---------------------------------------------------------------------------
// Kernel 1: x NCHW f32 -> NHWC fp16 quantized (proven R10/R12/R14 version)
// ---------------------------------------------------------------------------
__global__ void __launch_bounds__(128) pack_x_kernel(const float* __restrict__ x) {
    __shared__ float tile[32][60];
    const int b = blockIdx.x / HW, h = blockIdx.x % HW;
    const int ch0 = blockIdx.y * 32;
    const int t = threadIdx.x;
#pragma unroll
    for (int j = 0; j < 4; ++j) {
        int idx = t + j * 128;
        if (idx >= 32 * 14) break;
        int c = idx / 14, f4 = idx % 14;
        float4 v = *(const float4*)&x[((b * CIN + ch0 + c) * HW + h) * HW + f4 * 4];
        tile[c][f4 * 4 + 0] = v.x; tile[c][f4 * 4 + 1] = v.y;
        tile[c][f4 * 4 + 2] = v.z; tile[c][f4 * 4 + 3] = v.w;
    }
    __syncthreads();
#pragma unroll
    for (int j = 0; j < 2; ++j) {
        int i = t + j * 128;
        if (i >= HW * 4) break;
        int chunk = i / HW, w = i % HW;
        int c0 = chunk * 8;
        uint4 vv;
        unsigned* pv = (unsigned*)&vv;
#pragma unroll
        for (int k = 0; k < 4; ++k) {
            float q0 = rintf(tile[c0 + 2 * k][w] * 255.0f);
            float q1 = rintf(tile[c0 + 2 * k + 1][w] * 255.0f);
            q0 = fminf(fmaxf(q0, 0.0f), 255.0f);
            q1 = fminf(fmaxf(q1, 0.0f), 255.0f);
            __half2 h2 = __floats2half2_rn(q0, q1);
            pv[k] = *(unsigned*)&h2;
        }
        *(uint4*)&g_xh[((b * HW + h) * HW + w) * CIN + ch0 + c0] = vv;
    }
}

// ---------------------------------------------------------------------------
// Kernel 2: pcilt[...,1]/256 -> [tap][o][c] fp16 (exact: integer x 2^-8)
// ---------------------------------------------------------------------------
__global__ void pack_w_kernel(const float* __restrict__ pcilt) {
    int idx = blockIdx.x * 256 + threadIdx.x;
    if (idx >= 9 * COUT * CIN) return;
    int c   = idx % CIN;
    int o   = (idx / CIN) % COUT;
    int tap = idx / (CIN * COUT);
    long long p = (((long long)(o * CIN + c)) * 9 + tap) * 256 + 1;
    g_wh[(tap * COUT + o) * CIN + c] = __float2half_rn(pcilt[p] * 0.00390625f);
}

// ---------------------------------------------------------------------------
// Kernel 3: role-swapped HMMA conv with fp16 ACCUMULATION (2x tensor rate
// hypothesis). Per 32-ch chunk: 2 mma steps accumulate in fp16 (exact inputs,
// bounded <= 8128 << 65504), then promote to fp32. Unscale x256 in epilogue.
//   CTA = M64 oc x N112 px, 4 warps (32oc x 56px), 2-slot W ring, 2 CTAs/SM.
// ---------------------------------------------------------------------------
#define PXS       272
#define X_PX      232
#define WST       272
#define SMEM_SX   0
#define SMEM_W0   (X_PX * PXS)                     // 63104
#define W_SLOT_SZ (64 * WST)                       // 17408
#define SMEM_MB   (SMEM_W0 + 2 * W_SLOT_SZ)        // 97920
#define SMEM_SZ   (SMEM_MB + 64)
#define NTHR      128

// fp16-accumulate MMA: D(f16x2 x2) = A*B + C
#define HMMA16_INIT(c0, c1, a, b, z) \
    asm volatile( \
        "mma.sync.aligned.m16n8k16.row.col.f16.f16.f16.f16 " \
        "{%0,%1}, {%2,%3,%4,%5}, {%6,%7}, {%8,%8};" \
        : "=r"(c0), "=r"(c1) \
        : "r"((a)[0]), "r"((a)[1]), "r"((a)[2]), "r"((a)[3]), \
          "r"((b)[0]), "r"((b)[1]), "r"(z))
#define HMMA16_ACC(c0, c1, a, b) \
    asm volatile( \
        "mma.sync.aligned.m16n8k16.row.col.f16.f16.f16.f16 " \
        "{%0,%1}, {%2,%3,%4,%5}, {%6,%7}, {%0,%1};" \
        : "+r"(c0), "+r"(c1) \
        : "r"((a)[0]), "r"((a)[1]), "r"((a)[2]), "r"((a)[3]), \
          "r"((b)[0]), "r"((b)[1]))
#define LDSM4(r0, r1, r2, r3, addr) \
    asm volatile("ldmatrix.sync.aligned.m8n8.x4.shared.b16 {%0,%1,%2,%3}, [%4];" \
        : "=r"(r0), "=r"(r1), "=r"(r2), "=r"(r3) : "r"(addr))
#define LDSM2(r0, r1, addr) \
    asm volatile("ldmatrix.sync.aligned.m8n8.x2.shared.b16 {%0,%1}, [%2];" \
        : "=r"(r0), "=r"(r1) : "r"(addr))
#define CPASYNC(dst, src, sz) \
    asm volatile("cp.async.cg.shared.global [%0], [%1], 16, %2;" :: "r"(dst), "l"(src), "r"(sz))
#define MBAR_INIT(a, n) asm volatile("mbarrier.init.shared.b64 [%0], %1;" :: "r"(a), "r"(n) : "memory")
#define MBAR_ARRIVE(a)  asm volatile("mbarrier.arrive.shared.b64 _, [%0];" :: "r"(a) : "memory")
#define CP_MBAR_ARRIVE(a) \
    asm volatile("cp.async.mbarrier.arrive.noinc.shared.b64 [%0];" :: "r"(a) : "memory")
#define MBAR_WAIT(a, ph) do {                                                     \
    uint32_t _m = (a), _p = (uint32_t)(ph), _d;                                   \
    asm volatile("{ .reg .pred p; mbarrier.try_wait.parity.acquire.cta.shared::cta.b64 p, [%1], %2; selp.b32 %0,1,0,p; }" \
        : "=r"(_d) : "r"(_m), "r"(_p) : "memory");                                \
    if (!_d) {                                                                    \
        asm volatile("{ .reg .pred P1; WL_%=: mbarrier.try_wait.parity.acquire.cta.shared::cta.b64 P1, [%0], %1, 0x989680;" \
            " @P1 bra.uni WD_%=; bra.uni WL_%=; WD_%=: }" :: "r"(_m), "r"(_p) : "memory"); \
    } } while (0)

__global__ void __launch_bounds__(NTHR, 2)
conv_hmma_kernel(const float* __restrict__ bias, float* __restrict__ out) {
    extern __shared__ __align__(16) unsigned char smem[];
    const uint32_t sb = smem_u32(smem);

    const int t    = threadIdx.x;
    const int wid  = t >> 5;
    const int lane = t & 31;
    const int ocbase = blockIdx.x * 64;
    const int h0     = blockIdx.y * 2;
    const int b      = blockIdx.z;

    const uint32_t mb_full  = sb + SMEM_MB;
    const uint32_t mb_empty = sb + SMEM_MB + 16;

    if (t == 0) {
#pragma unroll
        for (int s = 0; s < 2; ++s) {
            MBAR_INIT(mb_full + s * 8, NTHR);
            MBAR_INIT(mb_empty + s * 8, NTHR);
        }
    }
    __syncthreads();

    // ---- Prologue: X halo tile + W taps 0,1 ----
    for (int i = t; i < X_PX * 16; i += NTHR) {
        int px = i >> 4, chunk = i & 15;
        int row = px / 58, col = px % 58;
        int h_in = h0 + row - 1, w_in = col - 1;
        bool ok = (h_in >= 0) && (h_in < HW) && (w_in >= 0) && (w_in < HW);
        const __half* src = ok ? &g_xh[((b * HW + h_in) * HW + w_in) * CIN + chunk * 8] : g_xh;
        CPASYNC(sb + SMEM_SX + px * PXS + chunk * 16, src, ok ? 16 : 0);
    }
#pragma unroll
    for (int tap = 0; tap < 2; ++tap) {
        uint32_t wdst = sb + SMEM_W0 + tap * W_SLOT_SZ;
#pragma unroll
        for (int j = 0; j < 8; ++j) {
            int i = t + j * NTHR;
            int o = i >> 4, chunk = i & 15;
            CPASYNC(wdst + o * WST + chunk * 16,
                    &g_wh[(tap * COUT + ocbase + o) * CIN + chunk * 8], 16);
        }
        CP_MBAR_ARRIVE(mb_full + tap * 8);
    }

    const int wm = (wid >> 1) * 32;
    const int wn = (wid & 1) * 56;

    float acc[2][7][4];
#pragma unroll
    for (int mt = 0; mt < 2; ++mt)
#pragma unroll
        for (int nt = 0; nt < 7; ++nt)
#pragma unroll
            for (int k = 0; k < 4; ++k) acc[mt][nt][k] = 0.0f;

    const int g = lane >> 3;
    const uint32_t a_lane = (uint32_t)(wm + ((g & 1) * 8) + (lane & 7)) * WST + (g >> 1) * 16;
    auto px_addr = [&](int px) -> uint32_t {
        int r = px / 56, w = px % 56;
        return sb + SMEM_SX + (uint32_t)(r * 58 + w) * PXS;
    };
    const int pxl = (lane & 7);
    const uint32_t bp0 = px_addr(wn + ((g >> 1) + 0) * 8 + pxl) + (g & 1) * 16;
    const uint32_t bp1 = px_addr(wn + ((g >> 1) + 2) * 8 + pxl) + (g & 1) * 16;
    const uint32_t bp2 = px_addr(wn + ((g >> 1) + 4) * 8 + pxl) + (g & 1) * 16;
    const uint32_t bp3 = px_addr(wn + 48 + pxl) + ((lane >> 3) & 1) * 16;

#pragma unroll 1
    for (int tap = 0; tap < 9; ++tap) {
        const int kh = tap / 3, kw = tap % 3;
        const int slot = tap & 1;
        const uint32_t aw = sb + SMEM_W0 + slot * W_SLOT_SZ + a_lane;
        const uint32_t toff = (uint32_t)(kh * 58 + kw) * PXS;

        MBAR_WAIT(mb_full + slot * 8, (tap >> 1) & 1);

        // 4 chunks of 2 K-steps; fp16 accumulate within chunk, promote after.
#pragma unroll
        for (int ks2 = 0; ks2 < 4; ++ks2) {
            const int k0 = ks2 * 64;          // 2 ks * 32B
            unsigned a[2][4], bf[7][2];
            unsigned c16[2][7][2];

            // --- ks = 2*ks2 : D = A*B + 0 ---
            LDSM4(a[0][0], a[0][1], a[0][2], a[0][3], aw + k0);
            LDSM4(a[1][0], a[1][1], a[1][2], a[1][3], aw + 16 * WST + k0);
            LDSM4(bf[0][0], bf[0][1], bf[1][0], bf[1][1], bp0 + toff + k0);
            LDSM4(bf[2][0], bf[2][1], bf[3][0], bf[3][1], bp1 + toff + k0);
            LDSM4(bf[4][0], bf[4][1], bf[5][0], bf[5][1], bp2 + toff + k0);
            LDSM2(bf[6][0], bf[6][1], bp3 + toff + k0);
#pragma unroll
            for (int mt = 0; mt < 2; ++mt)
#pragma unroll
                for (int nt = 0; nt < 7; ++nt)
                    HMMA16_INIT(c16[mt][nt][0], c16[mt][nt][1], a[mt], bf[nt], 0u);

            // --- ks = 2*ks2+1 : D += A*B ---
            LDSM4(a[0][0], a[0][1], a[0][2], a[0][3], aw + k0 + 32);
            LDSM4(a[1][0], a[1][1], a[1][2], a[1][3], aw + 16 * WST + k0 + 32);
            LDSM4(bf[0][0], bf[0][1], bf[1][0], bf[1][1], bp0 + toff + k0 + 32);
            LDSM4(bf[2][0], bf[2][1], bf[3][0], bf[3][1], bp1 + toff + k0 + 32);
            LDSM4(bf[4][0], bf[4][1], bf[5][0], bf[5][1], bp2 + toff + k0 + 32);
            LDSM2(bf[6][0], bf[6][1], bp3 + toff + k0 + 32);
#pragma unroll
            for (int mt = 0; mt < 2; ++mt)
#pragma unroll
                for (int nt = 0; nt < 7; ++nt)
                    HMMA16_ACC(c16[mt][nt][0], c16[mt][nt][1], a[mt], bf[nt]);

            // --- promote chunk to fp32 ---
#pragma unroll
            for (int mt = 0; mt < 2; ++mt)
#pragma unroll
                for (int nt = 0; nt < 7; ++nt) {
                    float2 lo = __half22float2(*(__half2*)&c16[mt][nt][0]);
                    float2 hi = __half22float2(*(__half2*)&c16[mt][nt][1]);
                    acc[mt][nt][0] += lo.x;
                    acc[mt][nt][1] += lo.y;
                    acc[mt][nt][2] += hi.x;
                    acc[mt][nt][3] += hi.y;
                }
        }

        MBAR_ARRIVE(mb_empty + slot * 8);

        if (tap <= 6) {
            MBAR_WAIT(mb_empty + slot * 8, (tap >> 1) & 1);
            uint32_t wdst = sb + SMEM_W0 + slot * W_SLOT_SZ;
#pragma unroll
            for (int j = 0; j < 8; ++j) {
                int i = t + j * NTHR;
                int o = i >> 4, chunk = i & 15;
                CPASYNC(wdst + o * WST + chunk * 16,
                        &g_wh[((tap + 2) * COUT + ocbase + o) * CIN + chunk * 8], 16);
            }
            CP_MBAR_ARRIVE(mb_full + slot * 8);
        }
    }

    // ---- Epilogue: unscale x256, add bias, direct NCHW float2 stores ----
    const int r  = wid & 1;
    const int hrow = h0 + r;
#pragma unroll
    for (int mt = 0; mt < 2; ++mt) {
        const int oc0 = ocbase + wm + mt * 16 + (lane >> 2);
        const float bv0 = bias[oc0];
        const float bv8 = bias[oc0 + 8];
        float* p0 = out + (((long long)b * COUT + oc0) * HW + hrow) * HW;
        float* p8 = out + (((long long)b * COUT + oc0 + 8) * HW + hrow) * HW;
#pragma unroll
        for (int nt = 0; nt < 7; ++nt) {
            const int w = nt * 8 + (lane & 3) * 2;
            float2 v0 = make_float2(fmaf(acc[mt][nt][0], 256.0f, bv0),
                                    fmaf(acc[mt][nt][1], 256.0f, bv0));
            float2 v8 = make_float2(fmaf(acc[mt][nt][2], 256.0f, bv8),
                                    fmaf(acc[mt][nt][3], 256.0f, bv8));
            *(float2*)(p0 + w) = v0;
            *(float2*)(p8 + w) = v8;
        }
    }
}

// ---------------------------------------------------------------------------
extern "C" void kernel_launch(void* const* d_in, const int* in_sizes, int n_in,
                              void* d_out, int out_size) {
    const float* x = nullptr;
    const float* pcilt = nullptr;
    const float* bias = nullptr;
    for (int i = 0; i < n_in; ++i) {
        if (in_sizes[i] == COUT) bias = (const float*)d_in[i];
        else if (in_sizes[i] == BATCH * CIN * HW * HW) x = (const float*)d_in[i];
        else pcilt = (const float*)d_in[i];
    }
    float* out = (float*)d_out;

    {
        dim3 g(BATCH * HW, 4);
        pack_x_kernel<<<g, 128>>>(x);
    }
    {
        int n = 9 * COUT * CIN;
        pack_w_kernel<<<(n + 255) / 256, 256>>>(pcilt);
    }
    {
        cudaFuncSetAttribute(conv_hmma_kernel,
                             cudaFuncAttributeMaxDynamicSharedMemorySize, SMEM_SZ);
        dim3 grid(COUT / 64, HW / 2, BATCH);   // (4, 28, 16) = 1792 CTAs, 2/SM
        conv_hmma_kernel<<<grid, NTHR, SMEM_SZ>>>(bias, out);
    }
    (void)out_size;
}